// round 14
// baseline (speedup 1.0000x reference)
#include <cuda_runtime.h>
#include <math.h>

// Problem shapes (fixed by the dataset)
#define N_SRC 8
#define B 4
#define T 2048
#define H 2048
#define THREADS 512          // H/4 floats per thread
#define NROWS (B * T)        // 8192 (b,t) rows total
#define EPS 1e-6f
#define PITCH 16
#define CTAS_PER_SM 2

__device__ __forceinline__ void prefetch_l2(const void* p) {
    asm volatile("prefetch.global.L2 [%0];" :: "l"(p));
}

// ---------------------------------------------------------------------------
// Persistent-CTA router (R13 skeleton + rotated loop).
// Per row:
//  - ROTATED: row r+1's 8 x LDG.128 issue right after routed is computed,
//    BEFORE the stores (reads enter LSU ahead of store-queue pressure)
//  - L2 prefetch 2 rows ahead (measured optimum)
//  - fold-reduce (16 SHFL/thread) + 1 barrier/row (double-buffered red[])
//  - column-sum split across half-warps (8 LDS chain + 1 SHFL)
//  - lane-specialized softmax (3 MUFU warp-insts), no max-subtraction
// ---------------------------------------------------------------------------
__global__ __launch_bounds__(THREADS, CTAS_PER_SM)
void router_kernel(const float* __restrict__ values,
                   const float* __restrict__ wq,
                   const float* __restrict__ bias,
                   const int* __restrict__ pos_ptr,
                   float* __restrict__ out_routed,   // [B][T][H]
                   float* __restrict__ out_alpha,    // [B][T][N_SRC]
                   int n_cta) {
    const int tid  = threadIdx.x;
    const int warp = tid >> 5, lane = tid & 31;
    const int pos  = pos_ptr ? *pos_ptr : N_SRC;
    const int j    = tid << 2;                      // float index within row

    // contiguous strip assignment: first `rem` CTAs get qn+1 rows
    const int qn  = NROWS / n_cta;
    const int rem = NROWS - qn * n_cta;
    const int cta = blockIdx.x;
    const int r0  = cta * qn + min(cta, rem);
    const int r1  = r0 + qn + (cta < rem ? 1 : 0);

    __shared__ float red[2][16 * PITCH];            // double-buffered per-warp totals
    __shared__ float cbred[16][N_SRC + 1];
    __shared__ float cb_s[N_SRC];

    const float4 q = *(const float4*)(wq + (size_t)pos * H + j);
    const size_t nstr = (size_t)B * T * H;          // n stride in values

    // prefetch mapping: thread tid covers one 128B line of the target row
    const int pf_n   = tid >> 6;
    const int pf_off = (tid & 63) << 5;             // *32 floats = 128B line
    const float* pfb = values + (size_t)pf_n * nstr + pf_off;

    const float inv_sqrt_h = rsqrtf((float)H);
    const float inv_h = 1.0f / (float)H;

    // ---- prologue: prefetch + first row's loads + per-CTA cbias ----
    if (r0 + 1 < r1) prefetch_l2(pfb + (size_t)(r0 + 1) * H);
    if (r0 + 2 < r1) prefetch_l2(pfb + (size_t)(r0 + 2) * H);

    // row r0's loads issue first; cbias below overlaps their DRAM latency
    float4 v[N_SRC];
    #pragma unroll
    for (int n = 0; n < N_SRC; n++)
        v[n] = __ldcs((const float4*)(values + (size_t)r0 * H + (size_t)n * nstr + j));

    {
        float cb[N_SRC];
        #pragma unroll
        for (int n = 0; n < N_SRC; n++) {
            const float4 bv = __ldg((const float4*)(bias + (size_t)n * H + j));
            cb[n] = q.x*bv.x + q.y*bv.y + q.z*bv.z + q.w*bv.w;
        }
        #pragma unroll
        for (int n = 0; n < N_SRC; n++) {
            #pragma unroll
            for (int o = 16; o; o >>= 1)
                cb[n] += __shfl_xor_sync(0xffffffffu, cb[n], o);
        }
        if (lane == 0) {
            #pragma unroll
            for (int n = 0; n < N_SRC; n++)
                cbred[warp][n] = cb[n];
        }
        __syncthreads();
        if (warp == 0 && lane < N_SRC) {
            float s = 0.f;
            #pragma unroll
            for (int w = 0; w < 16; w++) s += cbred[w][lane];
            cb_s[lane] = s * inv_sqrt_h;
        }
        __syncthreads();
    }

    // ---- main loop (rotated: v holds row r at loop top) ----
    for (int r = r0; r < r1; r++) {
        const size_t rbase = (size_t)r * H;

        // prefetch row r+2 into L2 (in flight through the reduce tail)
        if (r + 2 < r1)
            prefetch_l2(pfb + (size_t)(r + 2) * H);

        // per-thread partials: val[0..7] = sum(v^2), val[8..15] = q.v
        float val[16];
        #pragma unroll
        for (int n = 0; n < N_SRC; n++) {
            const float4 x = v[n];
            val[n]     = x.x*x.x + x.y*x.y + x.z*x.z + x.w*x.w;
            val[8 + n] = q.x*x.x + q.y*x.y + q.z*x.z + q.w*x.w;
        }

        // fold-reduce: halve value count each level (16 SHFL total)
        {   // o=16: keep 8
            const bool bit = (lane & 16) != 0;
            #pragma unroll
            for (int k = 0; k < 8; k++) {
                const float send = bit ? val[k] : val[8 + k];
                const float recv = __shfl_xor_sync(0xffffffffu, send, 16);
                val[k] = (bit ? val[8 + k] : val[k]) + recv;
            }
        }
        {   // o=8: keep 4
            const bool bit = (lane & 8) != 0;
            #pragma unroll
            for (int k = 0; k < 4; k++) {
                const float send = bit ? val[k] : val[4 + k];
                const float recv = __shfl_xor_sync(0xffffffffu, send, 8);
                val[k] = (bit ? val[4 + k] : val[k]) + recv;
            }
        }
        {   // o=4: keep 2
            const bool bit = (lane & 4) != 0;
            #pragma unroll
            for (int k = 0; k < 2; k++) {
                const float send = bit ? val[k] : val[2 + k];
                const float recv = __shfl_xor_sync(0xffffffffu, send, 4);
                val[k] = (bit ? val[2 + k] : val[k]) + recv;
            }
        }
        float t;
        {   // o=2: keep 1
            const bool bit = (lane & 2) != 0;
            const float send = bit ? val[0] : val[1];
            const float recv = __shfl_xor_sync(0xffffffffu, send, 2);
            t = (bit ? val[1] : val[0]) + recv;
        }
        t += __shfl_xor_sync(0xffffffffu, t, 1);
        // lane L now holds warp total of value index (L>>1)

        float* rb = red[r & 1];
        if ((lane & 1) == 0)
            rb[warp * PITCH + (lane >> 1)] = t;
        __syncthreads();                            // the only barrier per row

        // column-sum split across half-warps:
        // lanes 0-15 sum warps 0-7, lanes 16-31 sum warps 8-15, combine via SHFL
        float tk;
        {
            const int col = lane & 15;
            const int w0  = (lane & 16) >> 1;       // 0 or 8
            float p = 0.f;
            #pragma unroll
            for (int w = 0; w < 8; w++)
                p += rb[(w0 + w) * PITCH + col];
            tk = p + __shfl_xor_sync(0xffffffffu, p, 16);
        }

        // lane-specialized softmax: lane n (n<8) computes exp for source n only
        float e;
        {
            const float dotq = __shfl_sync(0xffffffffu, tk, 8 + (lane & 7));
            const float inv  = rsqrtf(tk * inv_h + EPS);          // 1 MUFU/warp
            e = __expf(dotq * inv * inv_sqrt_h + cb_s[lane & 7]); // 1 MUFU/warp
        }
        // sum over lanes 0..7 (butterfly within the 8-lane group)
        float s = e;
        s += __shfl_xor_sync(0xffffffffu, s, 4);
        s += __shfl_xor_sync(0xffffffffu, s, 2);
        s += __shfl_xor_sync(0xffffffffu, s, 1);
        const float rr = 1.0f / __shfl_sync(0xffffffffu, s, 0);

        // gather alphas (valid lanes 0..7 of e)
        float alpha[N_SRC];
        #pragma unroll
        for (int n = 0; n < N_SRC; n++)
            alpha[n] = __shfl_sync(0xffffffffu, e, n) * rr;

        // routed = sum_n alpha_n * v_n  (register-resident)
        float4 o;
        o.x = alpha[0]*v[0].x; o.y = alpha[0]*v[0].y;
        o.z = alpha[0]*v[0].z; o.w = alpha[0]*v[0].w;
        #pragma unroll
        for (int n = 1; n < N_SRC; n++) {
            o.x += alpha[n]*v[n].x;
            o.y += alpha[n]*v[n].y;
            o.z += alpha[n]*v[n].z;
            o.w += alpha[n]*v[n].w;
        }

        // v is dead: issue next row's loads BEFORE the stores
        if (r + 1 < r1) {
            const size_t nb = (size_t)(r + 1) * H;
            #pragma unroll
            for (int n = 0; n < N_SRC; n++)
                v[n] = __ldcs((const float4*)(values + nb + (size_t)n * nstr + j));
        }

        __stcs((float4*)(out_routed + rbase + j), o);
        if (tid < N_SRC)
            out_alpha[(size_t)r * N_SRC + tid] = alpha[tid];
    }
}

// ---------------------------------------------------------------------------
// kernel_launch
// inputs: [0] values f32 [8,4,2048,2048], [1] w_query f32 [12,2048],
//         [2] key_pos_bias f32 [12,2048], [3] position i32 scalar
// output: routed f32 [4,2048,2048] followed by alpha f32 [4,2048,8]
// ---------------------------------------------------------------------------
extern "C" void kernel_launch(void* const* d_in, const int* in_sizes, int n_in,
                              void* d_out, int out_size) {
    const float* values = (const float*)d_in[0];
    const float* wq     = (const float*)d_in[1];
    const float* bias   = (const float*)d_in[2];
    const int*   pos    = (n_in > 3) ? (const int*)d_in[3] : nullptr;

    float* out_routed = (float*)d_out;
    float* out_alpha  = (float*)d_out + (size_t)B * T * H;

    static int n_cta = 0;
    if (n_cta == 0) {
        int dev = 0, nsm = 148;
        cudaGetDevice(&dev);
        cudaDeviceGetAttribute(&nsm, cudaDevAttrMultiProcessorCount, dev);
        n_cta = nsm * CTAS_PER_SM;
    }

    router_kernel<<<n_cta, THREADS>>>(values, wq, bias, pos,
                                      out_routed, out_alpha, n_cta);
}

// round 15
// speedup vs baseline: 1.0096x; 1.0096x over previous
#include <cuda_runtime.h>
#include <math.h>

// Problem shapes (fixed by the dataset)
#define N_SRC 8
#define B 4
#define T 2048
#define H 2048
#define THREADS 512          // H/4 floats per thread
#define NROWS (B * T)        // 8192 (b,t) rows total
#define EPS 1e-6f
#define PITCH 16
#define CTAS_PER_SM 2

__device__ __forceinline__ void prefetch_l2(const void* p) {
    asm volatile("prefetch.global.L2 [%0];" :: "l"(p));
}

// ---------------------------------------------------------------------------
// Persistent-CTA router (R13 configuration — measured session optimum).
// Per row:
//  - loads at loop TOP (8 x LDG.128, front-batched)
//  - L2 prefetch 2 rows ahead (measured optimum)
//  - fold-reduce (16 SHFL/thread) + 1 barrier/row (double-buffered red[])
//  - column-sum split across half-warps (8 LDS chain + 1 SHFL)
//  - lane-specialized softmax (3 MUFU warp-insts), no max-subtraction
//  - out_alpha stored before the routed FMA chain (retires under it)
// ---------------------------------------------------------------------------
__global__ __launch_bounds__(THREADS, CTAS_PER_SM)
void router_kernel(const float* __restrict__ values,
                   const float* __restrict__ wq,
                   const float* __restrict__ bias,
                   const int* __restrict__ pos_ptr,
                   float* __restrict__ out_routed,   // [B][T][H]
                   float* __restrict__ out_alpha,    // [B][T][N_SRC]
                   int n_cta) {
    const int tid  = threadIdx.x;
    const int warp = tid >> 5, lane = tid & 31;
    const int pos  = pos_ptr ? *pos_ptr : N_SRC;
    const int j    = tid << 2;                      // float index within row

    // contiguous strip assignment: first `rem` CTAs get qn+1 rows
    const int qn  = NROWS / n_cta;
    const int rem = NROWS - qn * n_cta;
    const int cta = blockIdx.x;
    const int r0  = cta * qn + min(cta, rem);
    const int r1  = r0 + qn + (cta < rem ? 1 : 0);

    __shared__ float red[2][16 * PITCH];            // double-buffered per-warp totals
    __shared__ float cbred[16][N_SRC + 1];
    __shared__ float cb_s[N_SRC];

    const float4 q = *(const float4*)(wq + (size_t)pos * H + j);
    const size_t nstr = (size_t)B * T * H;          // n stride in values

    // prefetch mapping: thread tid covers one 128B line of the target row
    const int pf_n   = tid >> 6;
    const int pf_off = (tid & 63) << 5;             // *32 floats = 128B line
    const float* pfb = values + (size_t)pf_n * nstr + pf_off;

    const float inv_sqrt_h = rsqrtf((float)H);
    const float inv_h = 1.0f / (float)H;

    // ---- prologue: prefetch first rows + per-CTA cbias ----
    if (r0 + 1 < r1) prefetch_l2(pfb + (size_t)(r0 + 1) * H);
    if (r0 + 2 < r1) prefetch_l2(pfb + (size_t)(r0 + 2) * H);

    {
        float cb[N_SRC];
        #pragma unroll
        for (int n = 0; n < N_SRC; n++) {
            const float4 bv = __ldg((const float4*)(bias + (size_t)n * H + j));
            cb[n] = q.x*bv.x + q.y*bv.y + q.z*bv.z + q.w*bv.w;
        }
        #pragma unroll
        for (int n = 0; n < N_SRC; n++) {
            #pragma unroll
            for (int o = 16; o; o >>= 1)
                cb[n] += __shfl_xor_sync(0xffffffffu, cb[n], o);
        }
        if (lane == 0) {
            #pragma unroll
            for (int n = 0; n < N_SRC; n++)
                cbred[warp][n] = cb[n];
        }
        __syncthreads();
        if (warp == 0 && lane < N_SRC) {
            float s = 0.f;
            #pragma unroll
            for (int w = 0; w < 16; w++) s += cbred[w][lane];
            cb_s[lane] = s * inv_sqrt_h;
        }
        __syncthreads();
    }

    // ---- main loop over this CTA's strip ----
    for (int r = r0; r < r1; r++) {
        const size_t rbase = (size_t)r * H;

        // front-batched loads of this row (8 x LDG.128)
        float4 v[N_SRC];
        #pragma unroll
        for (int n = 0; n < N_SRC; n++)
            v[n] = __ldcs((const float4*)(values + rbase + (size_t)n * nstr + j));

        // prefetch row r+2 into L2 (in flight through the reduce tail)
        if (r + 2 < r1)
            prefetch_l2(pfb + (size_t)(r + 2) * H);

        // per-thread partials: val[0..7] = sum(v^2), val[8..15] = q.v
        float val[16];
        #pragma unroll
        for (int n = 0; n < N_SRC; n++) {
            const float4 x = v[n];
            val[n]     = x.x*x.x + x.y*x.y + x.z*x.z + x.w*x.w;
            val[8 + n] = q.x*x.x + q.y*x.y + q.z*x.z + q.w*x.w;
        }

        // fold-reduce: halve value count each level (16 SHFL total)
        {   // o=16: keep 8
            const bool bit = (lane & 16) != 0;
            #pragma unroll
            for (int k = 0; k < 8; k++) {
                const float send = bit ? val[k] : val[8 + k];
                const float recv = __shfl_xor_sync(0xffffffffu, send, 16);
                val[k] = (bit ? val[8 + k] : val[k]) + recv;
            }
        }
        {   // o=8: keep 4
            const bool bit = (lane & 8) != 0;
            #pragma unroll
            for (int k = 0; k < 4; k++) {
                const float send = bit ? val[k] : val[4 + k];
                const float recv = __shfl_xor_sync(0xffffffffu, send, 8);
                val[k] = (bit ? val[4 + k] : val[k]) + recv;
            }
        }
        {   // o=4: keep 2
            const bool bit = (lane & 4) != 0;
            #pragma unroll
            for (int k = 0; k < 2; k++) {
                const float send = bit ? val[k] : val[2 + k];
                const float recv = __shfl_xor_sync(0xffffffffu, send, 4);
                val[k] = (bit ? val[2 + k] : val[k]) + recv;
            }
        }
        float t;
        {   // o=2: keep 1
            const bool bit = (lane & 2) != 0;
            const float send = bit ? val[0] : val[1];
            const float recv = __shfl_xor_sync(0xffffffffu, send, 2);
            t = (bit ? val[1] : val[0]) + recv;
        }
        t += __shfl_xor_sync(0xffffffffu, t, 1);
        // lane L now holds warp total of value index (L>>1)

        float* rb = red[r & 1];
        if ((lane & 1) == 0)
            rb[warp * PITCH + (lane >> 1)] = t;
        __syncthreads();                            // the only barrier per row

        // column-sum split across half-warps:
        // lanes 0-15 sum warps 0-7, lanes 16-31 sum warps 8-15, combine via SHFL
        float tk;
        {
            const int col = lane & 15;
            const int w0  = (lane & 16) >> 1;       // 0 or 8
            float p = 0.f;
            #pragma unroll
            for (int w = 0; w < 8; w++)
                p += rb[(w0 + w) * PITCH + col];
            tk = p + __shfl_xor_sync(0xffffffffu, p, 16);
        }

        // lane-specialized softmax: lane n (n<8) computes exp for source n only
        float e;
        {
            const float dotq = __shfl_sync(0xffffffffu, tk, 8 + (lane & 7));
            const float inv  = rsqrtf(tk * inv_h + EPS);          // 1 MUFU/warp
            e = __expf(dotq * inv * inv_sqrt_h + cb_s[lane & 7]); // 1 MUFU/warp
        }
        // sum over lanes 0..7 (butterfly within the 8-lane group)
        float s = e;
        s += __shfl_xor_sync(0xffffffffu, s, 4);
        s += __shfl_xor_sync(0xffffffffu, s, 2);
        s += __shfl_xor_sync(0xffffffffu, s, 1);
        const float rr = 1.0f / __shfl_sync(0xffffffffu, s, 0);

        // gather alphas (valid lanes 0..7 of e)
        float alpha[N_SRC];
        #pragma unroll
        for (int n = 0; n < N_SRC; n++)
            alpha[n] = __shfl_sync(0xffffffffu, e, n) * rr;

        // alpha store issues first; it retires under the FMA chain below
        if (tid < N_SRC)
            out_alpha[(size_t)r * N_SRC + tid] = alpha[tid];

        // routed = sum_n alpha_n * v_n  (register-resident), streaming store
        float4 o;
        o.x = alpha[0]*v[0].x; o.y = alpha[0]*v[0].y;
        o.z = alpha[0]*v[0].z; o.w = alpha[0]*v[0].w;
        #pragma unroll
        for (int n = 1; n < N_SRC; n++) {
            o.x += alpha[n]*v[n].x;
            o.y += alpha[n]*v[n].y;
            o.z += alpha[n]*v[n].z;
            o.w += alpha[n]*v[n].w;
        }
        __stcs((float4*)(out_routed + rbase + j), o);
    }
}

// ---------------------------------------------------------------------------
// kernel_launch
// inputs: [0] values f32 [8,4,2048,2048], [1] w_query f32 [12,2048],
//         [2] key_pos_bias f32 [12,2048], [3] position i32 scalar
// output: routed f32 [4,2048,2048] followed by alpha f32 [4,2048,8]
// ---------------------------------------------------------------------------
extern "C" void kernel_launch(void* const* d_in, const int* in_sizes, int n_in,
                              void* d_out, int out_size) {
    const float* values = (const float*)d_in[0];
    const float* wq     = (const float*)d_in[1];
    const float* bias   = (const float*)d_in[2];
    const int*   pos    = (n_in > 3) ? (const int*)d_in[3] : nullptr;

    float* out_routed = (float*)d_out;
    float* out_alpha  = (float*)d_out + (size_t)B * T * H;

    static int n_cta = 0;
    if (n_cta == 0) {
        int dev = 0, nsm = 148;
        cudaGetDevice(&dev);
        cudaDeviceGetAttribute(&nsm, cudaDevAttrMultiProcessorCount, dev);
        n_cta = nsm * CTAS_PER_SM;
    }

    router_kernel<<<n_cta, THREADS>>>(values, wq, bias, pos,
                                      out_routed, out_alpha, n_cta);
}